// round 17
// baseline (speedup 1.0000x reference)
#include <cuda_runtime.h>
#include <cuda_bf16.h>
#include <math.h>
#include <cstdint>

// ---------------- problem constants ----------------
#define EDIM 1024
#define NH   16
#define HD   64
#define TLEN 2048
#define SLEN 2048
#define BSZ  2
#define NZ   (BSZ*NH)    // 32
#define MTOK (TLEN*BSZ)  // 4096
#define SCALING 0.125f
#define DTHRESH 3.8918202981106265f

#define ATTN_ELEMS ((size_t)TLEN*BSZ*EDIM)
#define WEIGHT_ELEMS ((size_t)NZ*TLEN*SLEN)

// ---------------- scratch ----------------
static __device__ float g_Q[(size_t)NZ*TLEN*HD];      // [z][t][64]
static __device__ float g_K[(size_t)NZ*SLEN*HD];      // [z][s][64]
static __device__ float g_Vt[(size_t)NZ*HD*SLEN];     // [z][64][s]
static __device__ float g_S[(size_t)NZ*TLEN*SLEN];    // raw scores
static __device__ float g_A[(size_t)MTOK*EDIM];       // attn pre-out-proj [token][f]
static __device__ float g_rowM[(size_t)NZ*TLEN];      // per-row max
static __device__ float g_rowIS[(size_t)NZ*TLEN];     // per-row 1/sum

// ---------------- tile config ----------------
#define BM 128
#define BN 64
#define BK 32
#define ROWB 80            // smem row stride bytes (32 bf16 = 64B + 16 pad)

// per-stage smem sublayout (bytes)
#define ST_AH 0            // 128*80 = 10240
#define ST_AL 10240
#define ST_BH 20480        // 64*80 = 5120
#define ST_BL 25600
#define STAGE_B 30720      // one stage
#define SM_BIAS (2*STAGE_B)            // 61440
#define SM_STATS (2*STAGE_B + 256)     // 61696: 128 m + 128 invsum
#define SMEM_BYTES (2*STAGE_B + 256 + 1024)  // 62720
#define SM_STAGE 0                     // epilogue overlay (128*68*4 = 34816 < 61440)
#define STG_LD 68

__device__ __forceinline__ uint32_t smem_u32(const void* p) {
    uint32_t a;
    asm("{ .reg .u64 t; cvta.to.shared.u64 t, %1; cvt.u32.u64 %0, t; }" : "=r"(a) : "l"(p));
    return a;
}

__device__ __forceinline__ uint4 ldm_x4(uint32_t addr) {
    uint4 r;
    asm volatile("ldmatrix.sync.aligned.m8n8.x4.shared.b16 {%0,%1,%2,%3}, [%4];"
                 : "=r"(r.x), "=r"(r.y), "=r"(r.z), "=r"(r.w) : "r"(addr));
    return r;
}

__device__ __forceinline__ void mma16816(float* d, const uint4& a, uint32_t b0, uint32_t b1) {
    asm volatile("mma.sync.aligned.m16n8k16.row.col.f32.bf16.bf16.f32 "
                 "{%0,%1,%2,%3}, {%4,%5,%6,%7}, {%8,%9}, {%0,%1,%2,%3};"
                 : "+f"(d[0]), "+f"(d[1]), "+f"(d[2]), "+f"(d[3])
                 : "r"(a.x), "r"(a.y), "r"(a.z), "r"(a.w), "r"(b0), "r"(b1));
}

__device__ __forceinline__ void split2(float x, float y, uint32_t& hi, uint32_t& lo) {
    __nv_bfloat16 hx = __float2bfloat16(x);
    __nv_bfloat16 hy = __float2bfloat16(y);
    __nv_bfloat16 lx = __float2bfloat16(x - __bfloat162float(hx));
    __nv_bfloat16 ly = __float2bfloat16(y - __bfloat162float(hy));
    hi = (uint32_t)__bfloat16_as_ushort(hx) | ((uint32_t)__bfloat16_as_ushort(hy) << 16);
    lo = (uint32_t)__bfloat16_as_ushort(lx) | ((uint32_t)__bfloat16_as_ushort(ly) << 16);
}

// score -> prob transform (mask, dynamic threshold, exp, normalize)
__device__ __forceinline__ float4 prob4(float4 x, int4 mk, float mM, float mIS) {
    const float thr = mM - DTHRESH;
    float4 p;
    p.x = (mk.x == 0 || x.x < thr) ? 0.0f : __expf(x.x - mM) * mIS;
    p.y = (mk.y == 0 || x.y < thr) ? 0.0f : __expf(x.y - mM) * mIS;
    p.z = (mk.z == 0 || x.z < thr) ? 0.0f : __expf(x.z - mM) * mIS;
    p.w = (mk.w == 0 || x.w < thr) ? 0.0f : __expf(x.w - mM) * mIS;
    return p;
}

// ============================================================================
// Unified GEMM:  C[BMxBN] = A[BM x K] * B[BN x K]^T   (both K-contiguous)
// MODE 0: proj -> plain [token][1024]
// MODE 1: proj -> per-head q/k  [z][t][64]
// MODE 2: proj -> Vt            [z][64][s]
// MODE 3: QK   -> scores        [z][t][s]
// MODE 5: fused softmax+PV: A = raw scores, transformed at STS using rowstats;
//         optional export of normalized probs; attn -> [token][1024]
// bf16 2-way split (3 products), double-buffered smem, register prefetch.
// ============================================================================
template <int MODE>
__global__ __launch_bounds__(256, 2)
void mma_gemm(const float* __restrict__ Abase, const float* __restrict__ Bbase,
              const float* __restrict__ bias, float* __restrict__ out,
              float scale, int lda, int ldb, int Ktot,
              const int* __restrict__ maskp = nullptr,
              const float* __restrict__ rowM = nullptr,
              const float* __restrict__ rowIS = nullptr,
              float* __restrict__ expW = nullptr)
{
    extern __shared__ char sm[];
    const uint32_t smb = smem_u32(sm);
    const int tid = threadIdx.x;
    const int lane = tid & 31, wid = tid >> 5;
    const int wm = (wid & 3) * 32;
    const int wn = (wid >> 2) * 32;

    const int m0 = blockIdx.y * BM;
    const int n0 = blockIdx.x * BN;
    const int z  = blockIdx.z;

    const float* Ag;
    const float* Bg;
    if (MODE == 3) {
        Ag = Abase + ((size_t)z * TLEN + m0) * HD;
        Bg = Bbase + ((size_t)z * SLEN + n0) * HD;
    } else if (MODE == 5) {
        Ag = Abase + ((size_t)z * TLEN + m0) * SLEN;
        Bg = Bbase + (size_t)z * HD * SLEN;
    } else {
        Ag = Abase + (size_t)m0 * lda;
        Bg = Bbase + (size_t)n0 * ldb;
    }

    if (MODE <= 2) {
        if (tid < 64) ((float*)(sm + SM_BIAS))[tid] = bias[n0 + tid];
    }

    float* sM  = (float*)(sm + SM_STATS);
    float* sIS = sM + 128;
    if (MODE == 5) {
        if (tid < 128) {
            sM[tid]  = rowM[(size_t)z * TLEN + m0 + tid];
            sIS[tid] = rowIS[(size_t)z * TLEN + m0 + tid];
        }
        __syncthreads();
    }

    float d[2][4][4] = {};
    float4 pa[4], pb[2];

    const int nk = Ktot / BK;

    // ---- prologue: load + store chunk 0 ----
    #pragma unroll
    for (int i = 0; i < 4; i++) {
        const int idx = tid + i * 256;
        const int r = idx >> 3, c4 = (idx & 7) << 2;
        pa[i] = *(const float4*)(Ag + (size_t)r * lda + c4);
    }
    #pragma unroll
    for (int i = 0; i < 2; i++) {
        const int idx = tid + i * 256;
        const int r = idx >> 3, c4 = (idx & 7) << 2;
        pb[i] = *(const float4*)(Bg + (size_t)r * ldb + c4);
    }
    {
        char* st = sm;   // stage 0
        #pragma unroll
        for (int i = 0; i < 4; i++) {
            const int idx = tid + i * 256;
            const int r = idx >> 3, c4 = (idx & 7) << 2;
            float4 v = pa[i];
            if (MODE == 5) {
                int4 mk = *(const int4*)(maskp + (size_t)(m0 + r) * SLEN + c4);
                v = prob4(v, mk, sM[r], sIS[r]);
                if (expW)
                    *(float4*)(expW + ((size_t)z * TLEN + m0 + r) * SLEN + c4) = v;
            }
            uint32_t h0, l0, h1, l1;
            split2(v.x, v.y, h0, l0);
            split2(v.z, v.w, h1, l1);
            const int off = r * ROWB + c4 * 2;
            *(uint2*)(st + ST_AH + off) = make_uint2(h0, h1);
            *(uint2*)(st + ST_AL + off) = make_uint2(l0, l1);
        }
        #pragma unroll
        for (int i = 0; i < 2; i++) {
            const int idx = tid + i * 256;
            const int r = idx >> 3, c4 = (idx & 7) << 2;
            uint32_t h0, l0, h1, l1;
            split2(pb[i].x, pb[i].y, h0, l0);
            split2(pb[i].z, pb[i].w, h1, l1);
            const int off = r * ROWB + c4 * 2;
            *(uint2*)(st + ST_BH + off) = make_uint2(h0, h1);
            *(uint2*)(st + ST_BL + off) = make_uint2(l0, l1);
        }
    }
    __syncthreads();

    int cur = 0;
    for (int kc = 0; kc < nk; kc++) {
        const bool more = (kc + 1 < nk);
        const int k0n = (kc + 1) * BK;
        // ---- prefetch next chunk into registers (overlaps with mma below) ----
        if (more) {
            #pragma unroll
            for (int i = 0; i < 4; i++) {
                const int idx = tid + i * 256;
                const int r = idx >> 3, c4 = (idx & 7) << 2;
                pa[i] = *(const float4*)(Ag + (size_t)r * lda + k0n + c4);
            }
            #pragma unroll
            for (int i = 0; i < 2; i++) {
                const int idx = tid + i * 256;
                const int r = idx >> 3, c4 = (idx & 7) << 2;
                pb[i] = *(const float4*)(Bg + (size_t)r * ldb + k0n + c4);
            }
        }

        // ---- mma on current stage ----
        const uint32_t sb = smb + cur * STAGE_B;
        #pragma unroll
        for (int ks = 0; ks < 2; ks++) {
            uint4 ah[2], al[2];
            {
                const int arow_g = ((lane >> 3) & 1) * 8 + (lane & 7);
                const int akb = ks * 32 + (lane >> 4) * 16;
                #pragma unroll
                for (int mt = 0; mt < 2; mt++) {
                    const int off = (wm + mt * 16 + arow_g) * ROWB + akb;
                    ah[mt] = ldm_x4(sb + ST_AH + off);
                    al[mt] = ldm_x4(sb + ST_AL + off);
                }
            }
            uint4 bh[2], bl[2];
            {
                const int brow_g = (lane >> 4) * 8 + (lane & 7);
                const int bkb = ks * 32 + ((lane >> 3) & 1) * 16;
                #pragma unroll
                for (int np = 0; np < 2; np++) {
                    const int off = (wn + np * 16 + brow_g) * ROWB + bkb;
                    bh[np] = ldm_x4(sb + ST_BH + off);
                    bl[np] = ldm_x4(sb + ST_BL + off);
                }
            }
            #pragma unroll
            for (int mt = 0; mt < 2; mt++) {
                #pragma unroll
                for (int nt = 0; nt < 4; nt++) {
                    const uint4& BH = bh[nt >> 1];
                    const uint4& BL = bl[nt >> 1];
                    const uint32_t bh0 = (nt & 1) ? BH.z : BH.x;
                    const uint32_t bh1 = (nt & 1) ? BH.w : BH.y;
                    const uint32_t bl0 = (nt & 1) ? BL.z : BL.x;
                    const uint32_t bl1 = (nt & 1) ? BL.w : BL.y;
                    mma16816(d[mt][nt], ah[mt], bh0, bh1);
                    mma16816(d[mt][nt], ah[mt], bl0, bl1);
                    mma16816(d[mt][nt], al[mt], bh0, bh1);
                }
            }
        }

        // ---- store prefetched chunk into alternate stage ----
        if (more) {
            char* st = sm + (cur ^ 1) * STAGE_B;
            #pragma unroll
            for (int i = 0; i < 4; i++) {
                const int idx = tid + i * 256;
                const int r = idx >> 3, c4 = (idx & 7) << 2;
                float4 v = pa[i];
                if (MODE == 5) {
                    int4 mk = *(const int4*)(maskp + (size_t)(m0 + r) * SLEN + k0n + c4);
                    v = prob4(v, mk, sM[r], sIS[r]);
                    if (expW)
                        *(float4*)(expW + ((size_t)z * TLEN + m0 + r) * SLEN + k0n + c4) = v;
                }
                uint32_t h0, l0, h1, l1;
                split2(v.x, v.y, h0, l0);
                split2(v.z, v.w, h1, l1);
                const int off = r * ROWB + c4 * 2;
                *(uint2*)(st + ST_AH + off) = make_uint2(h0, h1);
                *(uint2*)(st + ST_AL + off) = make_uint2(l0, l1);
            }
            #pragma unroll
            for (int i = 0; i < 2; i++) {
                const int idx = tid + i * 256;
                const int r = idx >> 3, c4 = (idx & 7) << 2;
                uint32_t h0, l0, h1, l1;
                split2(pb[i].x, pb[i].y, h0, l0);
                split2(pb[i].z, pb[i].w, h1, l1);
                const int off = r * ROWB + c4 * 2;
                *(uint2*)(st + ST_BH + off) = make_uint2(h0, h1);
                *(uint2*)(st + ST_BL + off) = make_uint2(l0, l1);
            }
        }
        __syncthreads();
        cur ^= 1;
    }

    // ---- stage accumulators to smem ----
    float* stg = (float*)(sm + SM_STAGE);
    #pragma unroll
    for (int mt = 0; mt < 2; mt++) {
        #pragma unroll
        for (int nt = 0; nt < 4; nt++) {
            const int r = wm + mt * 16 + (lane >> 2);
            const int c = wn + nt * 8 + (lane & 3) * 2;
            stg[r * STG_LD + c]           = d[mt][nt][0];
            stg[r * STG_LD + c + 1]       = d[mt][nt][1];
            stg[(r + 8) * STG_LD + c]     = d[mt][nt][2];
            stg[(r + 8) * STG_LD + c + 1] = d[mt][nt][3];
        }
    }
    __syncthreads();

    const float* sBias = (const float*)(sm + SM_BIAS);

    if (MODE == 0 || MODE == 1) {
        #pragma unroll
        for (int i = 0; i < 8; i++) {
            const int idx = tid + i * 256;
            const int r = idx >> 4, c = (idx & 15) << 2;
            float4 v;
            v.x = (stg[r * STG_LD + c]     + sBias[c])     * scale;
            v.y = (stg[r * STG_LD + c + 1] + sBias[c + 1]) * scale;
            v.z = (stg[r * STG_LD + c + 2] + sBias[c + 2]) * scale;
            v.w = (stg[r * STG_LD + c + 3] + sBias[c + 3]) * scale;
            if (MODE == 0) {
                *(float4*)(out + (size_t)(m0 + r) * EDIM + n0 + c) = v;
            } else {
                const int row = m0 + r;
                const int t = row >> 1, b = row & 1;
                const int h = n0 >> 6;
                *(float4*)(out + ((size_t)(b * NH + h) * TLEN + t) * HD + c) = v;
            }
        }
    } else if (MODE == 2) {
        if (tid < 128) {
            const int c = tid >> 1, b = tid & 1;
            const int h = n0 >> 6;
            const float vb = sBias[c];
            float* o = out + ((size_t)((b * NH + h) * HD + c)) * SLEN + (m0 >> 1);
            #pragma unroll
            for (int j = 0; j < 64; j += 4) {
                float4 v;
                v.x = (stg[(2 * (j + 0) + b) * STG_LD + c] + vb) * scale;
                v.y = (stg[(2 * (j + 1) + b) * STG_LD + c] + vb) * scale;
                v.z = (stg[(2 * (j + 2) + b) * STG_LD + c] + vb) * scale;
                v.w = (stg[(2 * (j + 3) + b) * STG_LD + c] + vb) * scale;
                *(float4*)(o + j) = v;
            }
        }
    } else if (MODE == 3) {
        #pragma unroll
        for (int i = 0; i < 8; i++) {
            const int idx = tid + i * 256;
            const int r = idx >> 4, c = (idx & 15) << 2;
            float4 v = make_float4(stg[r * STG_LD + c], stg[r * STG_LD + c + 1],
                                   stg[r * STG_LD + c + 2], stg[r * STG_LD + c + 3]);
            *(float4*)(out + ((size_t)z * TLEN + m0 + r) * SLEN + n0 + c) = v;
        }
    } else { // MODE 5
        const int bb = z >> 4, hh = z & 15;
        #pragma unroll
        for (int i = 0; i < 8; i++) {
            const int idx = tid + i * 256;
            const int r = idx >> 4, c = (idx & 15) << 2;
            float4 v = make_float4(stg[r * STG_LD + c], stg[r * STG_LD + c + 1],
                                   stg[r * STG_LD + c + 2], stg[r * STG_LD + c + 3]);
            *(float4*)(out + ((size_t)(m0 + r) * BSZ + bb) * EDIM + hh * HD + c) = v;
        }
    }
}

// ============================================================================
// Row stats: per (z,t) row -> max (masked) and 1/sum of thresholded exps.
// ============================================================================
__global__ __launch_bounds__(256)
void rowstats_kernel(const float* __restrict__ Sin, const int* __restrict__ mask,
                     float* __restrict__ rowM, float* __restrict__ rowIS)
{
    const int row = blockIdx.x;
    const int t = row & (TLEN - 1);
    const int tid = threadIdx.x;
    const int lane = tid & 31, wid = tid >> 5;
    const float4* sr = (const float4*)(Sin + (size_t)row * SLEN);
    const int4*   mr = (const int4*)(mask + (size_t)t * SLEN);

    float4 v[2];
    float m = -INFINITY;
    #pragma unroll
    for (int i = 0; i < 2; i++) {
        const int q = tid + i * 256;
        float4 x = sr[q];
        int4 mk = mr[q];
        if (mk.x == 0) x.x = -INFINITY;
        if (mk.y == 0) x.y = -INFINITY;
        if (mk.z == 0) x.z = -INFINITY;
        if (mk.w == 0) x.w = -INFINITY;
        v[i] = x;
        m = fmaxf(m, fmaxf(fmaxf(x.x, x.y), fmaxf(x.z, x.w)));
    }

    __shared__ float red[8];
    #pragma unroll
    for (int off = 16; off > 0; off >>= 1)
        m = fmaxf(m, __shfl_xor_sync(0xFFFFFFFFu, m, off));
    if (lane == 0) red[wid] = m;
    __syncthreads();
    m = red[0];
    #pragma unroll
    for (int i = 1; i < 8; i++) m = fmaxf(m, red[i]);
    __syncthreads();

    const float thr = m - DTHRESH;
    float sum = 0.f;
    #pragma unroll
    for (int i = 0; i < 2; i++) {
        float4 x = v[i];
        sum += (x.x < thr) ? 0.0f : __expf(x.x - m);
        sum += (x.y < thr) ? 0.0f : __expf(x.y - m);
        sum += (x.z < thr) ? 0.0f : __expf(x.z - m);
        sum += (x.w < thr) ? 0.0f : __expf(x.w - m);
    }
    #pragma unroll
    for (int off = 16; off > 0; off >>= 1)
        sum += __shfl_xor_sync(0xFFFFFFFFu, sum, off);
    if (lane == 0) red[wid] = sum;
    __syncthreads();
    if (tid == 0) {
        sum = red[0];
        #pragma unroll
        for (int i = 1; i < 8; i++) sum += red[i];
        rowM[row] = m;
        rowIS[row] = 1.0f / sum;
    }
}

// ============================================================================
// Launch
// ============================================================================
extern "C" void kernel_launch(void* const* d_in, const int* in_sizes, int n_in,
                              void* d_out, int out_size)
{
    const float* query = (const float*)d_in[0];
    const float* key   = (const float*)d_in[1];
    const float* value = (const float*)d_in[2];
    const int*   mask  = (const int*)  d_in[3];
    const float* Wq    = (const float*)d_in[4];
    const float* bq    = (const float*)d_in[5];
    const float* Wk    = (const float*)d_in[6];
    const float* bk    = (const float*)d_in[7];
    const float* Wv    = (const float*)d_in[8];
    const float* bv    = (const float*)d_in[9];
    const float* Wo    = (const float*)d_in[10];
    const float* bo    = (const float*)d_in[11];
    float* out = (float*)d_out;

    float *pQ, *pK, *pVt, *pS, *pA, *pM, *pIS;
    cudaGetSymbolAddress((void**)&pQ,  g_Q);
    cudaGetSymbolAddress((void**)&pK,  g_K);
    cudaGetSymbolAddress((void**)&pVt, g_Vt);
    cudaGetSymbolAddress((void**)&pS,  g_S);
    cudaGetSymbolAddress((void**)&pA,  g_A);
    cudaGetSymbolAddress((void**)&pM,  g_rowM);
    cudaGetSymbolAddress((void**)&pIS, g_rowIS);

    const bool export_weights = ((size_t)out_size >= ATTN_ELEMS + WEIGHT_ELEMS);
    float* expW = export_weights ? (out + ATTN_ELEMS) : nullptr;

    static bool smem_set = false;
    if (!smem_set) {
        cudaFuncSetAttribute(mma_gemm<0>, cudaFuncAttributeMaxDynamicSharedMemorySize, SMEM_BYTES);
        cudaFuncSetAttribute(mma_gemm<1>, cudaFuncAttributeMaxDynamicSharedMemorySize, SMEM_BYTES);
        cudaFuncSetAttribute(mma_gemm<2>, cudaFuncAttributeMaxDynamicSharedMemorySize, SMEM_BYTES);
        cudaFuncSetAttribute(mma_gemm<3>, cudaFuncAttributeMaxDynamicSharedMemorySize, SMEM_BYTES);
        cudaFuncSetAttribute(mma_gemm<5>, cudaFuncAttributeMaxDynamicSharedMemorySize, SMEM_BYTES);
        smem_set = true;
    }

    dim3 gproj(EDIM / BN, MTOK / BM, 1);       // 16 x 32
    mma_gemm<1><<<gproj, 256, SMEM_BYTES>>>(query, Wq, bq, pQ,  SCALING, EDIM, EDIM, EDIM);
    mma_gemm<1><<<gproj, 256, SMEM_BYTES>>>(key,   Wk, bk, pK,  1.0f,    EDIM, EDIM, EDIM);
    mma_gemm<2><<<gproj, 256, SMEM_BYTES>>>(value, Wv, bv, pVt, 1.0f,    EDIM, EDIM, EDIM);

    dim3 gqk(SLEN / BN, TLEN / BM, NZ);        // 32 x 16 x 32
    mma_gemm<3><<<gqk, 256, SMEM_BYTES>>>(pQ, pK, nullptr, pS, 1.0f, HD, HD, HD);

    rowstats_kernel<<<NZ * TLEN, 256>>>(pS, mask, pM, pIS);

    dim3 gpv(1, TLEN / BM, NZ);                // 1 x 16 x 32
    mma_gemm<5><<<gpv, 256, SMEM_BYTES>>>(pS, pVt, nullptr, pA, 1.0f, SLEN, SLEN, SLEN,
                                          mask, pM, pIS, expW);

    mma_gemm<0><<<gproj, 256, SMEM_BYTES>>>(pA, Wo, bo, out, 1.0f, EDIM, EDIM, EDIM);
}